// round 2
// baseline (speedup 1.0000x reference)
#include <cuda_runtime.h>
#include <math.h>

// Problem constants (fixed by the dataset)
#define NMAX 100000
#define EMAX 1600000

// Scratch: __device__ globals (no allocation allowed in kernel_launch)
__device__ float g_deg [NMAX];
__device__ float g_dinv[NMAX];
__device__ float g_h   [NMAX * 64];   // post-GEMM features (messages)
__device__ float g_a   [NMAX * 64];   // aggregation buffer A
__device__ float g_b   [NMAX * 64];   // aggregation buffer B

// ---------------------------------------------------------------------------
// Degree / normalization
// ---------------------------------------------------------------------------
__global__ void init_deg_kernel(int n) {
    int i = blockIdx.x * blockDim.x + threadIdx.x;
    if (i < n) g_deg[i] = 1.0f;             // self loop
}

__global__ void count_deg_kernel(const int* __restrict__ dst, int E) {
    int i = blockIdx.x * blockDim.x + threadIdx.x;
    if (i < E) atomicAdd(&g_deg[dst[i]], 1.0f);
}

__global__ void dinv_kernel(int n) {
    int i = blockIdx.x * blockDim.x + threadIdx.x;
    if (i < n) g_dinv[i] = rsqrtf(g_deg[i]);   // deg >= 1 always
}

// ---------------------------------------------------------------------------
// Fused: H = (relu?)(X) @ W   and   A = bias + H * dinv^2  (self-loop term)
// X selected by xsel: -1 -> external ptr, 0 -> g_a, 1 -> g_b
// A output selected by osel: 0 -> g_a, 1 -> g_b
// blockDim = (64, 4): tx = output column, ty = row-within-block
// ---------------------------------------------------------------------------
__global__ void gemm64_kernel(const float* __restrict__ Xext, int xsel,
                              const float* __restrict__ W,
                              const float* __restrict__ bias,
                              int osel, int relu_in, int n)
{
    __shared__ float Ws[64 * 64];
    __shared__ float Xs[4][64];

    const float* X = (xsel < 0) ? Xext : (xsel == 0 ? g_a : g_b);
    float* A = (osel == 0) ? g_a : g_b;

    int c   = threadIdx.x;
    int ty  = threadIdx.y;
    int tid = ty * 64 + c;

    #pragma unroll
    for (int i = tid; i < 64 * 64; i += 256) Ws[i] = W[i];

    int row = blockIdx.x * 4 + ty;
    float xv = 0.0f;
    if (row < n) {
        xv = X[(size_t)row * 64 + c];
        if (relu_in) xv = fmaxf(xv, 0.0f);
    }
    Xs[ty][c] = xv;
    __syncthreads();

    if (row >= n) return;

    float acc = 0.0f;
    #pragma unroll
    for (int k = 0; k < 64; k++)
        acc = fmaf(Xs[ty][k], Ws[k * 64 + c], acc);

    g_h[(size_t)row * 64 + c] = acc;
    float di = g_dinv[row];
    A[(size_t)row * 64 + c] = bias[c] + acc * di * di;
}

// ---------------------------------------------------------------------------
// Edge scatter: A[dst] += h[src] * dinv[src]*dinv[dst]
// One thread per (edge, 4-float chunk): 16 threads cover an edge's 64 cols.
// Uses red.global.add.v4.f32 (no-return vector reduction).
// ---------------------------------------------------------------------------
__global__ void scatter_kernel(const int* __restrict__ src,
                               const int* __restrict__ dst,
                               int osel, int E)
{
    int idx = blockIdx.x * blockDim.x + threadIdx.x;
    int e = idx >> 4;
    if (e >= E) return;
    int c4 = (idx & 15) << 2;

    float* A = (osel == 0) ? g_a : g_b;

    int s = __ldg(src + e);
    int d = __ldg(dst + e);
    float nrm = __ldg(&g_dinv[s]) * __ldg(&g_dinv[d]);

    const float4 hv = *(const float4*)(g_h + (size_t)s * 64 + c4);
    float mx = hv.x * nrm, my = hv.y * nrm, mz = hv.z * nrm, mw = hv.w * nrm;

    float* p = A + (size_t)d * 64 + c4;
    asm volatile("red.global.add.v4.f32 [%0], {%1, %2, %3, %4};"
                 :: "l"(p), "f"(mx), "f"(my), "f"(mz), "f"(mw) : "memory");
}

// ---------------------------------------------------------------------------
// MLP head + log_softmax. One warp per node.
// hidden = relu( relu(x) @ Wp1 + bp1 )  [32]
// out    = hidden @ Wp2 + bp2           [40] -> log_softmax
// Input: g_a (final conv output, relu applied on load)
// ---------------------------------------------------------------------------
__global__ void mlp_head_kernel(const float* __restrict__ Wp1,
                                const float* __restrict__ bp1,
                                const float* __restrict__ Wp2,
                                const float* __restrict__ bp2,
                                float* __restrict__ out, int n)
{
    __shared__ float W1s[64 * 32];
    __shared__ float W2s[32 * 40];
    __shared__ float b1s[32];
    __shared__ float b2s[40];

    int tid = threadIdx.x;   // 256
    for (int i = tid; i < 64 * 32; i += 256) W1s[i] = Wp1[i];
    for (int i = tid; i < 32 * 40; i += 256) W2s[i] = Wp2[i];
    if (tid < 32) b1s[tid] = bp1[tid];
    if (tid < 40) b2s[tid] = bp2[tid];
    __syncthreads();

    int warp = tid >> 5;
    int lane = tid & 31;
    int node = blockIdx.x * 8 + warp;
    if (node >= n) return;

    float x0 = fmaxf(g_a[(size_t)node * 64 + lane], 0.0f);
    float x1 = fmaxf(g_a[(size_t)node * 64 + 32 + lane], 0.0f);

    // hidden[lane]
    float h = b1s[lane];
    #pragma unroll
    for (int k = 0; k < 32; k++) {
        float xk = __shfl_sync(0xffffffffu, x0, k);
        h = fmaf(xk, W1s[k * 32 + lane], h);
    }
    #pragma unroll
    for (int k = 0; k < 32; k++) {
        float xk = __shfl_sync(0xffffffffu, x1, k);
        h = fmaf(xk, W1s[(32 + k) * 32 + lane], h);
    }
    h = fmaxf(h, 0.0f);

    // outputs: lane -> class lane; lanes 0..7 also -> class 32+lane
    float o0 = b2s[lane];
    float o1 = (lane < 8) ? b2s[32 + lane] : 0.0f;
    #pragma unroll
    for (int j = 0; j < 32; j++) {
        float hj = __shfl_sync(0xffffffffu, h, j);
        o0 = fmaf(hj, W2s[j * 40 + lane], o0);
        if (lane < 8) o1 = fmaf(hj, W2s[j * 40 + 32 + lane], o1);
    }

    // log_softmax over the 40 values spread across the warp
    float m = (lane < 8) ? fmaxf(o0, o1) : o0;
    #pragma unroll
    for (int off = 16; off; off >>= 1)
        m = fmaxf(m, __shfl_xor_sync(0xffffffffu, m, off));

    float sum = expf(o0 - m) + ((lane < 8) ? expf(o1 - m) : 0.0f);
    #pragma unroll
    for (int off = 16; off; off >>= 1)
        sum += __shfl_xor_sync(0xffffffffu, sum, off);

    float lse = m + logf(sum);

    out[(size_t)node * 40 + lane] = o0 - lse;
    if (lane < 8)
        out[(size_t)node * 40 + 32 + lane] = o1 - lse;
}

// ---------------------------------------------------------------------------
// Launch
// ---------------------------------------------------------------------------
extern "C" void kernel_launch(void* const* d_in, const int* in_sizes, int n_in,
                              void* d_out, int out_size)
{
    const float* x   = (const float*)d_in[0];
    const int*   ei  = (const int*)  d_in[1];
    // d_in[2] = batch (unused)
    const float* W0  = (const float*)d_in[3];
    const float* b0  = (const float*)d_in[4];
    const float* W1  = (const float*)d_in[5];
    const float* b1  = (const float*)d_in[6];
    const float* W2  = (const float*)d_in[7];
    const float* b2  = (const float*)d_in[8];
    const float* Wp1 = (const float*)d_in[9];
    const float* bp1 = (const float*)d_in[10];
    const float* Wp2 = (const float*)d_in[11];
    const float* bp2 = (const float*)d_in[12];
    float* out = (float*)d_out;

    int n = in_sizes[0] / 64;
    int E = in_sizes[1] / 2;
    const int* src = ei;
    const int* dst = ei + E;

    dim3 gemm_block(64, 4);
    int gemm_grid    = (n + 3) / 4;
    int scatter_grid = (E * 16 + 255) / 256;

    // degree / normalization
    init_deg_kernel <<<(n + 255) / 256, 256>>>(n);
    count_deg_kernel<<<(E + 255) / 256, 256>>>(dst, E);
    dinv_kernel     <<<(n + 255) / 256, 256>>>(n);

    // layer 0: X = input x, out buf = A(g_a)
    gemm64_kernel <<<gemm_grid, gemm_block>>>(x, -1, W0, b0, /*osel=*/0, /*relu_in=*/0, n);
    scatter_kernel<<<scatter_grid, 256>>>(src, dst, /*osel=*/0, E);

    // layer 1: X = g_a (relu), out buf = B(g_b)
    gemm64_kernel <<<gemm_grid, gemm_block>>>(nullptr, 0, W1, b1, /*osel=*/1, /*relu_in=*/1, n);
    scatter_kernel<<<scatter_grid, 256>>>(src, dst, /*osel=*/1, E);

    // layer 2: X = g_b (relu), out buf = A(g_a)
    gemm64_kernel <<<gemm_grid, gemm_block>>>(nullptr, 1, W2, b2, /*osel=*/0, /*relu_in=*/1, n);
    scatter_kernel<<<scatter_grid, 256>>>(src, dst, /*osel=*/0, E);

    // head (reads g_a with relu)
    mlp_head_kernel<<<(n + 7) / 8, 256>>>(Wp1, bp1, Wp2, bp2, out, n);
}

// round 4
// speedup vs baseline: 1.0824x; 1.0824x over previous
#include <cuda_runtime.h>
#include <math.h>

#define NMAX 100000
#define EMAX 1600000
#define SCAN_T 1024

// Scratch (__device__ globals; no allocation allowed)
__device__ int   g_cnt[NMAX];          // in-degree (no self loop)
__device__ float g_dinv[NMAX];         // rsqrt(deg+1)
__device__ int   g_rowstart[NMAX + 1]; // CSR row offsets (by dst)
__device__ int   g_fill[NMAX];         // fill cursors
__device__ int2  g_csr[EMAX];          // packed (src, norm-as-int)
__device__ float g_a[NMAX * 64];
__device__ float g_b[NMAX * 64];

// ---------------------------------------------------------------------------
__global__ void zero_cnt_kernel(int n) {
    int i = blockIdx.x * blockDim.x + threadIdx.x;
    if (i < n) g_cnt[i] = 0;
}

__global__ void count_kernel(const int* __restrict__ dst, int E) {
    int i = blockIdx.x * blockDim.x + threadIdx.x;
    if (i < E) atomicAdd(&g_cnt[dst[i]], 1);
}

__global__ void dinv_kernel(int n) {
    int i = blockIdx.x * blockDim.x + threadIdx.x;
    if (i < n) g_dinv[i] = rsqrtf((float)g_cnt[i] + 1.0f);  // +1 self loop
}

// Single-block scan: row offsets + fill cursors
__global__ void scan_build_kernel(int n, int E) {
    __shared__ int sm[SCAN_T];
    int t = threadIdx.x;
    int chunk = (n + SCAN_T - 1) / SCAN_T;
    int beg = t * chunk;
    int end = min(n, beg + chunk);
    int s = 0;
    for (int i = beg; i < end; i++) s += g_cnt[i];
    sm[t] = s;
    __syncthreads();
    for (int off = 1; off < SCAN_T; off <<= 1) {
        int v = (t >= off) ? sm[t - off] : 0;
        __syncthreads();
        sm[t] += v;
        __syncthreads();
    }
    int run = sm[t] - s;  // exclusive base
    for (int i = beg; i < end; i++) {
        g_rowstart[i] = run;
        g_fill[i]     = run;
        run += g_cnt[i];
    }
    if (t == 0) g_rowstart[n] = E;
}

__global__ void fill_kernel(const int* __restrict__ src,
                            const int* __restrict__ dst, int E) {
    int e = blockIdx.x * blockDim.x + threadIdx.x;
    if (e >= E) return;
    int s = src[e], d = dst[e];
    float nrm = g_dinv[s] * g_dinv[d];
    int pos = atomicAdd(&g_fill[d], 1);
    g_csr[pos] = make_int2(s, __float_as_int(nrm));
}

// ---------------------------------------------------------------------------
// Fused GCN layer: y[i] = relu( (dinv_i^2 * x_i + sum_j nrm_ij x_j) @ W + b )
// One warp per node; lane owns feature pairs (2l, 2l+1) during aggregation,
// then output columns (l, l+32) for the transform.
// ---------------------------------------------------------------------------
__global__ void layer_kernel(const float* __restrict__ Xext, int xsel,
                             const float* __restrict__ W,
                             const float* __restrict__ bias,
                             int osel, int n)
{
    __shared__ float Ws[64 * 64];
    int tid = threadIdx.x;
    for (int i = tid; i < 64 * 64; i += 256) Ws[i] = W[i];

    const float* X = (xsel < 0) ? Xext : (xsel == 0 ? g_a : g_b);
    float* Y = (osel == 0) ? g_a : g_b;
    __syncthreads();

    int warp = tid >> 5, lane = tid & 31;
    int node = blockIdx.x * 8 + warp;
    if (node >= n) return;

    const float2* X2 = (const float2*)X;
    float di = g_dinv[node];
    float2 xx = X2[(size_t)node * 32 + lane];
    float ax = di * di * xx.x;
    float ay = di * di * xx.y;

    int beg = g_rowstart[node], end = g_rowstart[node + 1];
    int j = beg;
    for (; j + 1 < end; j += 2) {
        int2 e0 = g_csr[j];
        int2 e1 = g_csr[j + 1];
        float2 v0 = X2[(size_t)e0.x * 32 + lane];
        float2 v1 = X2[(size_t)e1.x * 32 + lane];
        float n0 = __int_as_float(e0.y);
        float n1 = __int_as_float(e1.y);
        ax = fmaf(n0, v0.x, ax); ax = fmaf(n1, v1.x, ax);
        ay = fmaf(n0, v0.y, ay); ay = fmaf(n1, v1.y, ay);
    }
    if (j < end) {
        int2 e = g_csr[j];
        float2 v = X2[(size_t)e.x * 32 + lane];
        float nm = __int_as_float(e.y);
        ax = fmaf(nm, v.x, ax);
        ay = fmaf(nm, v.y, ay);
    }

    // Transform: y[c] = sum_k agg[k] * W[k][c], c = lane, lane+32
    float y0 = bias[lane];
    float y1 = bias[lane + 32];
    #pragma unroll
    for (int k = 0; k < 32; k++) {
        float vx = __shfl_sync(0xffffffffu, ax, k);
        float vy = __shfl_sync(0xffffffffu, ay, k);
        y0 = fmaf(vx, Ws[(2 * k) * 64 + lane], y0);
        y0 = fmaf(vy, Ws[(2 * k + 1) * 64 + lane], y0);
        y1 = fmaf(vx, Ws[(2 * k) * 64 + 32 + lane], y1);
        y1 = fmaf(vy, Ws[(2 * k + 1) * 64 + 32 + lane], y1);
    }
    y0 = fmaxf(y0, 0.0f);
    y1 = fmaxf(y1, 0.0f);
    Y[(size_t)node * 64 + lane]      = y0;
    Y[(size_t)node * 64 + 32 + lane] = y1;
}

// ---------------------------------------------------------------------------
// MLP head + log_softmax. One warp per node. Input g_a (already relu'd).
// ---------------------------------------------------------------------------
__global__ void mlp_head_kernel(const float* __restrict__ Wp1,
                                const float* __restrict__ bp1,
                                const float* __restrict__ Wp2,
                                const float* __restrict__ bp2,
                                float* __restrict__ out, int n)
{
    __shared__ float W1s[64 * 32];
    __shared__ float W2s[32 * 40];
    __shared__ float b1s[32];
    __shared__ float b2s[40];

    int tid = threadIdx.x;
    for (int i = tid; i < 64 * 32; i += 256) W1s[i] = Wp1[i];
    for (int i = tid; i < 32 * 40; i += 256) W2s[i] = Wp2[i];
    if (tid < 32) b1s[tid] = bp1[tid];
    if (tid < 40) b2s[tid] = bp2[tid];
    __syncthreads();

    int warp = tid >> 5, lane = tid & 31;
    int node = blockIdx.x * 8 + warp;
    if (node >= n) return;

    float x0 = g_a[(size_t)node * 64 + lane];
    float x1 = g_a[(size_t)node * 64 + 32 + lane];

    float h = b1s[lane];
    #pragma unroll
    for (int k = 0; k < 32; k++) {
        float xk = __shfl_sync(0xffffffffu, x0, k);
        h = fmaf(xk, W1s[k * 32 + lane], h);
    }
    #pragma unroll
    for (int k = 0; k < 32; k++) {
        float xk = __shfl_sync(0xffffffffu, x1, k);
        h = fmaf(xk, W1s[(32 + k) * 32 + lane], h);
    }
    h = fmaxf(h, 0.0f);

    float o0 = b2s[lane];
    float o1 = (lane < 8) ? b2s[32 + lane] : 0.0f;
    #pragma unroll
    for (int j = 0; j < 32; j++) {
        float hj = __shfl_sync(0xffffffffu, h, j);
        o0 = fmaf(hj, W2s[j * 40 + lane], o0);
        if (lane < 8) o1 = fmaf(hj, W2s[j * 40 + 32 + lane], o1);
    }

    float m = (lane < 8) ? fmaxf(o0, o1) : o0;
    #pragma unroll
    for (int off = 16; off; off >>= 1)
        m = fmaxf(m, __shfl_xor_sync(0xffffffffu, m, off));

    float sum = expf(o0 - m) + ((lane < 8) ? expf(o1 - m) : 0.0f);
    #pragma unroll
    for (int off = 16; off; off >>= 1)
        sum += __shfl_xor_sync(0xffffffffu, sum, off);

    float lse = m + logf(sum);

    out[(size_t)node * 40 + lane] = o0 - lse;
    if (lane < 8)
        out[(size_t)node * 40 + 32 + lane] = o1 - lse;
}

// ---------------------------------------------------------------------------
extern "C" void kernel_launch(void* const* d_in, const int* in_sizes, int n_in,
                              void* d_out, int out_size)
{
    const float* x   = (const float*)d_in[0];
    const int*   ei  = (const int*)  d_in[1];
    const float* W0  = (const float*)d_in[3];
    const float* b0  = (const float*)d_in[4];
    const float* W1  = (const float*)d_in[5];
    const float* b1  = (const float*)d_in[6];
    const float* W2  = (const float*)d_in[7];
    const float* b2  = (const float*)d_in[8];
    const float* Wp1 = (const float*)d_in[9];
    const float* bp1 = (const float*)d_in[10];
    const float* Wp2 = (const float*)d_in[11];
    const float* bp2 = (const float*)d_in[12];
    float* out = (float*)d_out;

    int n = in_sizes[0] / 64;
    int E = in_sizes[1] / 2;
    const int* src = ei;
    const int* dst = ei + E;

    int nb  = (n + 255) / 256;
    int eb  = (E + 255) / 256;
    int lay = (n + 7) / 8;

    // CSR build
    zero_cnt_kernel  <<<nb, 256>>>(n);
    count_kernel     <<<eb, 256>>>(dst, E);
    dinv_kernel      <<<nb, 256>>>(n);
    scan_build_kernel<<<1, SCAN_T>>>(n, E);
    fill_kernel      <<<eb, 256>>>(src, dst, E);

    // Fused GCN layers (aggregate-then-transform)
    layer_kernel<<<lay, 256>>>(x,       -1, W0, b0, /*osel=*/0, n);
    layer_kernel<<<lay, 256>>>(nullptr,  0, W1, b1, /*osel=*/1, n);
    layer_kernel<<<lay, 256>>>(nullptr,  1, W2, b2, /*osel=*/0, n);

    // Head
    mlp_head_kernel<<<lay, 256>>>(Wp1, bp1, Wp2, bp2, out, n);
}

// round 5
// speedup vs baseline: 1.4126x; 1.3050x over previous
#include <cuda_runtime.h>
#include <math.h>

#define NMAX 100000
#define EMAX 1600000
#define SCAN_B 1024                    // threads per scan block
#define NBLK ((NMAX + SCAN_B - 1) / SCAN_B)   // 98

// Scratch (__device__ globals; no allocation allowed)
__device__ int   g_cnt[NMAX];          // in-degree (no self loop)
__device__ float g_dinv[NMAX];         // rsqrt(deg+1)
__device__ int   g_rowstart[NMAX + 1]; // CSR row offsets (by dst)
__device__ int   g_fill[NMAX];         // fill cursors
__device__ int   g_bsum[NBLK + 1];     // per-block totals
__device__ int2  g_csr[EMAX];          // packed (src, norm-as-int)
__device__ float g_a[NMAX * 64];
__device__ float g_b[NMAX * 64];

// ---------------------------------------------------------------------------
__global__ void zero_cnt_kernel(int n) {
    int i = blockIdx.x * blockDim.x + threadIdx.x;
    if (i < n) g_cnt[i] = 0;
}

__global__ void count_kernel(const int* __restrict__ dst, int E) {
    int i = blockIdx.x * blockDim.x + threadIdx.x;
    if (i < E) atomicAdd(&g_cnt[dst[i]], 1);
}

__global__ void dinv_kernel(int n) {
    int i = blockIdx.x * blockDim.x + threadIdx.x;
    if (i < n) g_dinv[i] = rsqrtf((float)g_cnt[i] + 1.0f);  // +1 self loop
}

// ---------------------------------------------------------------------------
// Grid-wide exclusive scan of g_cnt -> g_rowstart, in 3 passes.
// ---------------------------------------------------------------------------
__global__ void scan_local_kernel(int n) {
    __shared__ int sm[SCAN_B];
    int t = threadIdx.x;
    int i = blockIdx.x * SCAN_B + t;
    int v = (i < n) ? g_cnt[i] : 0;
    sm[t] = v;
    __syncthreads();
    // Hillis-Steele inclusive scan
    #pragma unroll
    for (int off = 1; off < SCAN_B; off <<= 1) {
        int u = (t >= off) ? sm[t - off] : 0;
        __syncthreads();
        sm[t] += u;
        __syncthreads();
    }
    if (i < n) g_rowstart[i] = sm[t] - v;          // local exclusive
    if (t == SCAN_B - 1) g_bsum[blockIdx.x] = sm[t];
}

__global__ void scan_bsums_kernel(int nb) {
    __shared__ int sm[128];
    int t = threadIdx.x;
    int v = (t < nb) ? g_bsum[t] : 0;
    sm[t] = v;
    __syncthreads();
    #pragma unroll
    for (int off = 1; off < 128; off <<= 1) {
        int u = (t >= off) ? sm[t - off] : 0;
        __syncthreads();
        sm[t] += u;
        __syncthreads();
    }
    if (t < nb) g_bsum[t] = sm[t] - v;             // exclusive block offsets
}

__global__ void scan_apply_kernel(int n, int E) {
    int i = blockIdx.x * blockDim.x + threadIdx.x;
    if (i < n) {
        int r = g_rowstart[i] + g_bsum[blockIdx.x * blockDim.x / SCAN_B + (threadIdx.x / SCAN_B)];
        // blockDim == SCAN_B so the block offset index is just blockIdx.x:
        r = g_rowstart[i] + g_bsum[i / SCAN_B];
        g_rowstart[i] = r;
        g_fill[i] = r;
    }
    if (i == 0) g_rowstart[n] = E;
}

__global__ void fill_kernel(const int* __restrict__ src,
                            const int* __restrict__ dst, int E) {
    int e = blockIdx.x * blockDim.x + threadIdx.x;
    if (e >= E) return;
    int s = src[e], d = dst[e];
    float nrm = g_dinv[s] * g_dinv[d];
    int pos = atomicAdd(&g_fill[d], 1);
    g_csr[pos] = make_int2(s, __float_as_int(nrm));
}

// ---------------------------------------------------------------------------
// Fused GCN layer: y[i] = relu( (dinv_i^2 * x_i + sum_j nrm_ij x_j) @ W + b )
// One warp per node; lane owns feature pairs (2l, 2l+1) during aggregation,
// then output columns (l, l+32) for the transform.
// ---------------------------------------------------------------------------
__global__ void layer_kernel(const float* __restrict__ Xext, int xsel,
                             const float* __restrict__ W,
                             const float* __restrict__ bias,
                             int osel, int n)
{
    __shared__ float Ws[64 * 64];
    int tid = threadIdx.x;
    for (int i = tid; i < 64 * 64; i += 256) Ws[i] = W[i];

    const float* X = (xsel < 0) ? Xext : (xsel == 0 ? g_a : g_b);
    float* Y = (osel == 0) ? g_a : g_b;
    __syncthreads();

    int warp = tid >> 5, lane = tid & 31;
    int node = blockIdx.x * 8 + warp;
    if (node >= n) return;

    const float2* X2 = (const float2*)X;
    float di = g_dinv[node];
    float2 xx = X2[(size_t)node * 32 + lane];
    float ax = di * di * xx.x;
    float ay = di * di * xx.y;

    int beg = g_rowstart[node], end = g_rowstart[node + 1];
    int j = beg;
    for (; j + 1 < end; j += 2) {
        int2 e0 = g_csr[j];
        int2 e1 = g_csr[j + 1];
        float2 v0 = X2[(size_t)e0.x * 32 + lane];
        float2 v1 = X2[(size_t)e1.x * 32 + lane];
        float n0 = __int_as_float(e0.y);
        float n1 = __int_as_float(e1.y);
        ax = fmaf(n0, v0.x, ax); ax = fmaf(n1, v1.x, ax);
        ay = fmaf(n0, v0.y, ay); ay = fmaf(n1, v1.y, ay);
    }
    if (j < end) {
        int2 e = g_csr[j];
        float2 v = X2[(size_t)e.x * 32 + lane];
        float nm = __int_as_float(e.y);
        ax = fmaf(nm, v.x, ax);
        ay = fmaf(nm, v.y, ay);
    }

    // Transform: y[c] = sum_k agg[k] * W[k][c], c = lane, lane+32
    float y0 = bias[lane];
    float y1 = bias[lane + 32];
    #pragma unroll
    for (int k = 0; k < 32; k++) {
        float vx = __shfl_sync(0xffffffffu, ax, k);
        float vy = __shfl_sync(0xffffffffu, ay, k);
        y0 = fmaf(vx, Ws[(2 * k) * 64 + lane], y0);
        y0 = fmaf(vy, Ws[(2 * k + 1) * 64 + lane], y0);
        y1 = fmaf(vx, Ws[(2 * k) * 64 + 32 + lane], y1);
        y1 = fmaf(vy, Ws[(2 * k + 1) * 64 + 32 + lane], y1);
    }
    y0 = fmaxf(y0, 0.0f);
    y1 = fmaxf(y1, 0.0f);
    Y[(size_t)node * 64 + lane]      = y0;
    Y[(size_t)node * 64 + 32 + lane] = y1;
}

// ---------------------------------------------------------------------------
// MLP head + log_softmax. One warp per node. Input g_a (already relu'd).
// ---------------------------------------------------------------------------
__global__ void mlp_head_kernel(const float* __restrict__ Wp1,
                                const float* __restrict__ bp1,
                                const float* __restrict__ Wp2,
                                const float* __restrict__ bp2,
                                float* __restrict__ out, int n)
{
    __shared__ float W1s[64 * 32];
    __shared__ float W2s[32 * 40];
    __shared__ float b1s[32];
    __shared__ float b2s[40];

    int tid = threadIdx.x;
    for (int i = tid; i < 64 * 32; i += 256) W1s[i] = Wp1[i];
    for (int i = tid; i < 32 * 40; i += 256) W2s[i] = Wp2[i];
    if (tid < 32) b1s[tid] = bp1[tid];
    if (tid < 40) b2s[tid] = bp2[tid];
    __syncthreads();

    int warp = tid >> 5, lane = tid & 31;
    int node = blockIdx.x * 8 + warp;
    if (node >= n) return;

    float x0 = g_a[(size_t)node * 64 + lane];
    float x1 = g_a[(size_t)node * 64 + 32 + lane];

    float h = b1s[lane];
    #pragma unroll
    for (int k = 0; k < 32; k++) {
        float xk = __shfl_sync(0xffffffffu, x0, k);
        h = fmaf(xk, W1s[k * 32 + lane], h);
    }
    #pragma unroll
    for (int k = 0; k < 32; k++) {
        float xk = __shfl_sync(0xffffffffu, x1, k);
        h = fmaf(xk, W1s[(32 + k) * 32 + lane], h);
    }
    h = fmaxf(h, 0.0f);

    float o0 = b2s[lane];
    float o1 = (lane < 8) ? b2s[32 + lane] : 0.0f;
    #pragma unroll
    for (int j = 0; j < 32; j++) {
        float hj = __shfl_sync(0xffffffffu, h, j);
        o0 = fmaf(hj, W2s[j * 40 + lane], o0);
        if (lane < 8) o1 = fmaf(hj, W2s[j * 40 + 32 + lane], o1);
    }

    float m = (lane < 8) ? fmaxf(o0, o1) : o0;
    #pragma unroll
    for (int off = 16; off; off >>= 1)
        m = fmaxf(m, __shfl_xor_sync(0xffffffffu, m, off));

    float sum = expf(o0 - m) + ((lane < 8) ? expf(o1 - m) : 0.0f);
    #pragma unroll
    for (int off = 16; off; off >>= 1)
        sum += __shfl_xor_sync(0xffffffffu, sum, off);

    float lse = m + logf(sum);

    out[(size_t)node * 40 + lane] = o0 - lse;
    if (lane < 8)
        out[(size_t)node * 40 + 32 + lane] = o1 - lse;
}

// ---------------------------------------------------------------------------
extern "C" void kernel_launch(void* const* d_in, const int* in_sizes, int n_in,
                              void* d_out, int out_size)
{
    const float* x   = (const float*)d_in[0];
    const int*   ei  = (const int*)  d_in[1];
    const float* W0  = (const float*)d_in[3];
    const float* b0  = (const float*)d_in[4];
    const float* W1  = (const float*)d_in[5];
    const float* b1  = (const float*)d_in[6];
    const float* W2  = (const float*)d_in[7];
    const float* b2  = (const float*)d_in[8];
    const float* Wp1 = (const float*)d_in[9];
    const float* bp1 = (const float*)d_in[10];
    const float* Wp2 = (const float*)d_in[11];
    const float* bp2 = (const float*)d_in[12];
    float* out = (float*)d_out;

    int n = in_sizes[0] / 64;
    int E = in_sizes[1] / 2;
    const int* src = ei;
    const int* dst = ei + E;

    int nb   = (n + 255) / 256;
    int eb   = (E + 255) / 256;
    int lay  = (n + 7) / 8;
    int nb2  = (n + SCAN_B - 1) / SCAN_B;

    // CSR build
    zero_cnt_kernel  <<<nb, 256>>>(n);
    count_kernel     <<<eb, 256>>>(dst, E);
    dinv_kernel      <<<nb, 256>>>(n);
    scan_local_kernel<<<nb2, SCAN_B>>>(n);
    scan_bsums_kernel<<<1, 128>>>(nb2);
    scan_apply_kernel<<<nb2, SCAN_B>>>(n, E);
    fill_kernel      <<<eb, 256>>>(src, dst, E);

    // Fused GCN layers (aggregate-then-transform)
    layer_kernel<<<lay, 256>>>(x,       -1, W0, b0, /*osel=*/0, n);
    layer_kernel<<<lay, 256>>>(nullptr,  0, W1, b1, /*osel=*/1, n);
    layer_kernel<<<lay, 256>>>(nullptr,  1, W2, b2, /*osel=*/0, n);

    // Head
    mlp_head_kernel<<<lay, 256>>>(Wp1, bp1, Wp2, bp2, out, n);
}